// round 2
// baseline (speedup 1.0000x reference)
#include <cuda_runtime.h>
#include <cuda_bf16.h>

// Problem constants
#define BB     1024
#define SS     350
#define VOCAB  41
#define LAT    512
#define H1     256   // layer0 hidden
#define H2     128   // layer1 hidden
#define H3     32    // layer2 hidden
#define G0DIM  768   // 3*H1
#define G1DIM  384   // 3*H2
#define G2DIM  96    // 3*H3
#define INITD  416   // H1+H2+H3
#define BROWS  7
#define NCTA   147   // 147*7 = 1029 >= 1024
#define PRED_OFF (BB*SS*VOCAB)

// ------------------------- device scratch (static, no allocs) ---------------
__device__ float  g_G0[VOCAB * G0DIM];        // gi0 table: includes bih0
__device__ float  g_init[BB * INITD];         // initial hidden states
__device__ float4 g_Wt0 [64 * G0DIM];         // Whh0^T packed [k4][j] (K=256)
__device__ float4 g_Wt1 [64 * G1DIM];         // Wih1^T packed [k4][j] (K=256)
__device__ float4 g_Wt1h[32 * G1DIM];         // Whh1^T packed [k4][j] (K=128) -> smem
__device__ float  g_Wt2i[H2 * G2DIM];         // Wih2^T [k][j]
__device__ float  g_Wt2h[H3 * G2DIM];         // Whh2^T [k][j]
__device__ float  g_WtInit[LAT * INITD];      // W_init^T [k][o]
__device__ float  g_WtIh0[LAT * G0DIM];       // Wih0^T [k][j]

__device__ __forceinline__ float sigf(float x) { return 1.0f / (1.0f + __expf(-x)); }

// ------------------------- prep: transposes --------------------------------
__global__ void k_prep_wt0(const float* __restrict__ Whh0) {
    int idx = blockIdx.x * blockDim.x + threadIdx.x;       // j*64 + k4
    if (idx < G0DIM * 64) {
        int j = idx >> 6, k4 = idx & 63;
        const float* s = Whh0 + j * H1 + k4 * 4;
        g_Wt0[k4 * G0DIM + j] = make_float4(s[0], s[1], s[2], s[3]);
    }
}
__global__ void k_prep_wt1(const float* __restrict__ Wih1) {
    int idx = blockIdx.x * blockDim.x + threadIdx.x;       // j*64 + k4
    if (idx < G1DIM * 64) {
        int j = idx >> 6, k4 = idx & 63;
        const float* s = Wih1 + j * H1 + k4 * 4;
        g_Wt1[k4 * G1DIM + j] = make_float4(s[0], s[1], s[2], s[3]);
    }
}
__global__ void k_prep_wt1h(const float* __restrict__ Whh1) {
    int idx = blockIdx.x * blockDim.x + threadIdx.x;       // j*32 + k4
    if (idx < G1DIM * 32) {
        int j = idx >> 5, k4 = idx & 31;
        const float* s = Whh1 + j * H2 + k4 * 4;
        g_Wt1h[k4 * G1DIM + j] = make_float4(s[0], s[1], s[2], s[3]);
    }
}
__global__ void k_prep_wt2(const float* __restrict__ Wih2, const float* __restrict__ Whh2) {
    int idx = blockIdx.x * blockDim.x + threadIdx.x;
    if (idx < G2DIM * H2) {                                // Wih2: 96 x 128
        int j = idx / H2, k = idx % H2;
        g_Wt2i[k * G2DIM + j] = Wih2[idx];
    }
    if (idx < G2DIM * H3) {                                // Whh2: 96 x 32
        int j = idx / H3, k = idx % H3;
        g_Wt2h[k * G2DIM + j] = Whh2[idx];
    }
}
__global__ void k_prep_wtinit(const float* __restrict__ W_init) {
    int idx = blockIdx.x * blockDim.x + threadIdx.x;
    if (idx < INITD * LAT) {
        int o = idx / LAT, k = idx % LAT;
        g_WtInit[k * INITD + o] = W_init[idx];
    }
}
__global__ void k_prep_wtih0(const float* __restrict__ Wih0) {
    int idx = blockIdx.x * blockDim.x + threadIdx.x;
    if (idx < G0DIM * LAT) {
        int j = idx / LAT, k = idx % LAT;
        g_WtIh0[k * G0DIM + j] = Wih0[idx];
    }
}

// ------------------------- prep: G0 table + init state ----------------------
__global__ void k_g0(const float* __restrict__ W_emb, const float* __restrict__ b_emb,
                     const float* __restrict__ bih0) {
    __shared__ float emb[LAT];
    int v = blockIdx.x;
    for (int k = threadIdx.x; k < LAT; k += blockDim.x)
        emb[k] = W_emb[k * VOCAB + v] + b_emb[k];
    __syncthreads();
    for (int j = threadIdx.x; j < G0DIM; j += blockDim.x) {
        float acc = bih0[j];
        for (int k = 0; k < LAT; k++)
            acc += emb[k] * g_WtIh0[k * G0DIM + j];
        g_G0[v * G0DIM + j] = acc;
    }
}

__global__ void k_init(const float* __restrict__ latent, const float* __restrict__ b_init) {
    __shared__ float lat[8 * LAT];
    int b0 = blockIdx.x * 8;
    for (int i = threadIdx.x; i < 8 * LAT; i += 256) {
        int r = i >> 9, k = i & 511;
        lat[i] = latent[(b0 + r) * LAT + k];
    }
    __syncthreads();
    for (int o = threadIdx.x; o < INITD; o += 256) {
        float bi = b_init[o];
        float acc[8];
#pragma unroll
        for (int r = 0; r < 8; r++) acc[r] = bi;
        for (int k = 0; k < LAT; k++) {
            float w = g_WtInit[k * INITD + o];
#pragma unroll
            for (int r = 0; r < 8; r++) acc[r] += w * lat[(r << 9) + k];
        }
#pragma unroll
        for (int r = 0; r < 8; r++) g_init[(b0 + r) * INITD + o] = acc[r];
    }
}

// ------------------------- main persistent GRU kernel -----------------------
// smem float layout offsets
#define O_WHH1 0
#define O_PROJ 49152
#define O_H0   (O_PROJ + 1312)
#define O_H1   (O_H0 + BROWS * H1)
#define O_H2   (O_H1 + BROWS * H2)
#define O_LOG  (O_H2 + BROWS * H3)
#define O_TOK  (O_LOG + BROWS * 41 + 1)     // 288 region
#define SMEM_FLOATS (O_TOK + 8)
#define SMEM_BYTES  (SMEM_FLOATS * 4)

__global__ void __launch_bounds__(256, 1)
k_gru(const int* __restrict__ toks,
      const float* __restrict__ bhh0,
      const float* __restrict__ bih1, const float* __restrict__ bhh1,
      const float* __restrict__ bih2, const float* __restrict__ bhh2,
      const float* __restrict__ W_proj, const float* __restrict__ b_proj,
      float* __restrict__ out)
{
    extern __shared__ float sm[];
    float* sWhh1 = sm + O_WHH1;
    float* sProj = sm + O_PROJ;
    float* h0    = sm + O_H0;
    float* h1    = sm + O_H1;
    float* h2    = sm + O_H2;
    float* slog  = sm + O_LOG;
    int*   stok  = (int*)(sm + O_TOK);

    const int tid  = threadIdx.x;
    const int base = blockIdx.x * BROWS;

    // --- load Whh1^T (packed float4) into smem ---
    {
        float4* d = (float4*)sWhh1;
        for (int i = tid; i < 32 * G1DIM; i += 256) d[i] = g_Wt1h[i];
    }
    // --- load W_proj transposed into smem: sProj[k*41+o] ---
    for (int i = tid; i < VOCAB * H3; i += 256) {
        int o = i / H3, k = i % H3;
        sProj[k * VOCAB + o] = W_proj[i];
    }
    // --- load initial hidden states ---
#pragma unroll
    for (int r = 0; r < BROWS; r++) {
        int b = base + r; int bb = b < BB ? b : BB - 1;
        if (tid < H1) h0[r * H1 + tid] = g_init[bb * INITD + tid];
        if (tid < H2) h1[r * H2 + tid] = g_init[bb * INITD + H1 + tid];
        if (tid < H3) h2[r * H3 + tid] = g_init[bb * INITD + H1 + H2 + tid];
    }

    // --- hoist biases into registers ---
    const int i0 = tid;                  // layer0 unit
    float b0r = bhh0[i0], b0z = bhh0[H1 + i0], b0n = bhh0[2 * H1 + i0];

    float b1r = 0, b1z = 0, b1n = 0, b1hn = 0;
    if (tid < H2) {
        b1r  = bih1[tid] + bhh1[tid];
        b1z  = bih1[H2 + tid] + bhh1[H2 + tid];
        b1n  = bih1[2 * H2 + tid];
        b1hn = bhh1[2 * H2 + tid];
    }
    const int q2 = tid >> 5;             // layer2 row
    const int i2 = tid & 31;             // layer2 unit
    float b2r = 0, b2z = 0, b2n = 0, b2hn = 0;
    if (tid < BROWS * 32) {
        b2r  = bih2[i2] + bhh2[i2];
        b2z  = bih2[H3 + i2] + bhh2[H3 + i2];
        b2n  = bih2[2 * H3 + i2];
        b2hn = bhh2[2 * H3 + i2];
    }
    __syncthreads();

    for (int t = 0; t < SS; t++) {
        // tokens for this step
        if (tid < BROWS) {
            int b = base + tid; int bb = b < BB ? b : BB - 1;
            stok[tid] = (t == 0) ? 1 : toks[bb * SS + t];
        }
        __syncthreads();

        // ================= Layer 0: unit i0 = tid (256 units) ==============
        {
            float aR[BROWS], aZ[BROWS], aN[BROWS], giN[BROWS];
#pragma unroll
            for (int r = 0; r < BROWS; r++) {
                const float* g = g_G0 + stok[r] * G0DIM;
                aR[r]  = g[i0];
                aZ[r]  = g[H1 + i0];
                giN[r] = g[2 * H1 + i0];
                aN[r]  = 0.0f;
            }
            const float4* __restrict__ W = g_Wt0;
            for (int k4 = 0; k4 < 64; k4++) {
                float4 wr = W[k4 * G0DIM + i0];
                float4 wz = W[k4 * G0DIM + H1 + i0];
                float4 wn = W[k4 * G0DIM + 2 * H1 + i0];
#pragma unroll
                for (int r = 0; r < BROWS; r++) {
                    float4 h = *(const float4*)&h0[r * H1 + k4 * 4];
                    aR[r] += wr.x * h.x + wr.y * h.y + wr.z * h.z + wr.w * h.w;
                    aZ[r] += wz.x * h.x + wz.y * h.y + wz.z * h.z + wz.w * h.w;
                    aN[r] += wn.x * h.x + wn.y * h.y + wn.z * h.z + wn.w * h.w;
                }
            }
            __syncthreads();   // everyone done reading old h0
#pragma unroll
            for (int r = 0; r < BROWS; r++) {
                float rg = sigf(aR[r] + b0r);
                float zg = sigf(aZ[r] + b0z);
                float ng = tanhf(giN[r] + rg * (aN[r] + b0n));
                float hp = h0[r * H1 + i0];       // own element, safe
                h0[r * H1 + i0] = (1.0f - zg) * ng + zg * hp;
            }
        }
        __syncthreads();

        // ================= Layer 1: unit j = tid (threads 0..127) ==========
        {
            float aR[BROWS], aZ[BROWS], aN[BROWS], aHN[BROWS];
            if (tid < H2) {
#pragma unroll
                for (int r = 0; r < BROWS; r++) {
                    aR[r] = b1r; aZ[r] = b1z; aN[r] = b1n; aHN[r] = b1hn;
                }
                const int j = tid;
                const float4* __restrict__ Wi = g_Wt1;
                for (int k4 = 0; k4 < 64; k4++) {          // gi over h0 (K=256)
                    float4 wr = Wi[k4 * G1DIM + j];
                    float4 wz = Wi[k4 * G1DIM + H2 + j];
                    float4 wn = Wi[k4 * G1DIM + 2 * H2 + j];
#pragma unroll
                    for (int r = 0; r < BROWS; r++) {
                        float4 h = *(const float4*)&h0[r * H1 + k4 * 4];
                        aR[r] += wr.x * h.x + wr.y * h.y + wr.z * h.z + wr.w * h.w;
                        aZ[r] += wz.x * h.x + wz.y * h.y + wz.z * h.z + wz.w * h.w;
                        aN[r] += wn.x * h.x + wn.y * h.y + wn.z * h.z + wn.w * h.w;
                    }
                }
                const float4* __restrict__ Wh = (const float4*)sWhh1;
                for (int k4 = 0; k4 < 32; k4++) {          // gh over h1 (K=128)
                    float4 wr = Wh[k4 * G1DIM + j];
                    float4 wz = Wh[k4 * G1DIM + H2 + j];
                    float4 wn = Wh[k4 * G1DIM + 2 * H2 + j];
#pragma unroll
                    for (int r = 0; r < BROWS; r++) {
                        float4 h = *(const float4*)&h1[r * H2 + k4 * 4];
                        aR[r]  += wr.x * h.x + wr.y * h.y + wr.z * h.z + wr.w * h.w;
                        aZ[r]  += wz.x * h.x + wz.y * h.y + wz.z * h.z + wz.w * h.w;
                        aHN[r] += wn.x * h.x + wn.y * h.y + wn.z * h.z + wn.w * h.w;
                    }
                }
            }
            __syncthreads();   // readers of old h1 done
            if (tid < H2) {
                const int j = tid;
#pragma unroll
                for (int r = 0; r < BROWS; r++) {
                    float rg = sigf(aR[r]);
                    float zg = sigf(aZ[r]);
                    float ng = tanhf(aN[r] + rg * aHN[r]);
                    float hp = h1[r * H2 + j];
                    h1[r * H2 + j] = (1.0f - zg) * ng + zg * hp;
                }
            }
        }
        __syncthreads();

        // ================= Layer 2: (row q2, unit i2), threads 0..223 ======
        {
            float aR = 0, aZ = 0, aN = 0, aHN = 0;
            if (tid < BROWS * 32) {
                aR = b2r; aZ = b2z; aN = b2n; aHN = b2hn;
                for (int k = 0; k < H2; k++) {             // gi over h1 (K=128)
                    float x = h1[q2 * H2 + k];
                    aR += x * g_Wt2i[k * G2DIM + i2];
                    aZ += x * g_Wt2i[k * G2DIM + H3 + i2];
                    aN += x * g_Wt2i[k * G2DIM + 2 * H3 + i2];
                }
                for (int k = 0; k < H3; k++) {             // gh over h2 (K=32)
                    float hh = h2[q2 * H3 + k];
                    aR  += hh * g_Wt2h[k * G2DIM + i2];
                    aZ  += hh * g_Wt2h[k * G2DIM + H3 + i2];
                    aHN += hh * g_Wt2h[k * G2DIM + 2 * H3 + i2];
                }
            }
            __syncthreads();   // readers of old h2 done
            if (tid < BROWS * 32) {
                float rg = sigf(aR);
                float zg = sigf(aZ);
                float ng = tanhf(aN + rg * aHN);
                float hp = h2[q2 * H3 + i2];
                h2[q2 * H3 + i2] = (1.0f - zg) * ng + zg * hp;
            }
        }
        __syncthreads();

        // ================= logits + store ==================================
        {
#pragma unroll
            for (int rep = 0; rep < 2; rep++) {
                int idx = tid + rep * 256;
                if (idx < BROWS * VOCAB) {
                    int q = idx / VOCAB, o = idx % VOCAB;
                    float acc = b_proj[o];
#pragma unroll
                    for (int k = 0; k < H3; k++)
                        acc += h2[q * H3 + k] * sProj[k * VOCAB + o];
                    slog[q * VOCAB + o] = acc;
                    int b = base + q;
                    if (b < BB) out[(b * SS + t) * VOCAB + o] = acc;
                }
            }
        }
        __syncthreads();
        // argmax (first max index, matches jnp.argmax)
        if (tid < BROWS) {
            float best = slog[tid * VOCAB];
            int   bi   = 0;
            for (int o = 1; o < VOCAB; o++) {
                float v = slog[tid * VOCAB + o];
                if (v > best) { best = v; bi = o; }
            }
            int b = base + tid;
            if (b < BB) out[PRED_OFF + b * SS + t] = (float)bi;
        }
        __syncthreads();
    }
}

// ------------------------- launch -------------------------------------------
extern "C" void kernel_launch(void* const* d_in, const int* in_sizes, int n_in,
                              void* d_out, int out_size) {
    const float* latent  = (const float*)d_in[0];
    const int*   ttok    = (const int*)  d_in[1];
    const float* W_emb   = (const float*)d_in[2];
    const float* b_emb   = (const float*)d_in[3];
    const float* W_init  = (const float*)d_in[4];
    const float* b_init  = (const float*)d_in[5];
    const float* Wih0    = (const float*)d_in[6];
    const float* Whh0    = (const float*)d_in[7];
    const float* bih0    = (const float*)d_in[8];
    const float* bhh0    = (const float*)d_in[9];
    const float* Wih1    = (const float*)d_in[10];
    const float* Whh1    = (const float*)d_in[11];
    const float* bih1    = (const float*)d_in[12];
    const float* bhh1    = (const float*)d_in[13];
    const float* Wih2    = (const float*)d_in[14];
    const float* Whh2    = (const float*)d_in[15];
    const float* bih2    = (const float*)d_in[16];
    const float* bhh2    = (const float*)d_in[17];
    const float* W_proj  = (const float*)d_in[18];
    const float* b_proj  = (const float*)d_in[19];
    float* out = (float*)d_out;

    k_prep_wt0  <<<(G0DIM * 64 + 255) / 256, 256>>>(Whh0);
    k_prep_wt1  <<<(G1DIM * 64 + 255) / 256, 256>>>(Wih1);
    k_prep_wt1h <<<(G1DIM * 32 + 255) / 256, 256>>>(Whh1);
    k_prep_wt2  <<<(G2DIM * H2 + 255) / 256, 256>>>(Wih2, Whh2);
    k_prep_wtinit<<<(INITD * LAT + 255) / 256, 256>>>(W_init);
    k_prep_wtih0<<<(G0DIM * LAT + 255) / 256, 256>>>(Wih0);
    k_g0  <<<VOCAB, 256>>>(W_emb, b_emb, bih0);
    k_init<<<BB / 8, 256>>>(latent, b_init);

    cudaFuncSetAttribute(k_gru, cudaFuncAttributeMaxDynamicSharedMemorySize, SMEM_BYTES);
    k_gru<<<NCTA, 256, SMEM_BYTES>>>(ttok, bhh0, bih1, bhh1, bih2, bhh2,
                                     W_proj, b_proj, out);
}

// round 3
// speedup vs baseline: 1.4674x; 1.4674x over previous
#include <cuda_runtime.h>
#include <cuda_bf16.h>

// Problem constants
#define BB     1024
#define SS     350
#define VOCAB  41
#define LAT    512
#define H1     256
#define H2     128
#define H3     32
#define G0DIM  768   // 3*H1
#define G1DIM  384   // 3*H2
#define G2DIM  96    // 3*H3
#define INITD  416
#define BROWS  7
#define NCTA   147
#define NT     384
#define PRED_OFF (BB*SS*VOCAB)

typedef unsigned long long ull;

// ------------------------- device scratch -----------------------------------
__device__ float  g_G0[VOCAB * G0DIM];        // gi0 table (includes bih0)
__device__ float  g_init[BB * INITD];
__device__ float4 g_Wt0 [64 * G0DIM];         // Whh0^T  [k4][f], K=256
__device__ float4 g_Wt1 [64 * G1DIM];         // Wih1^T  [k4][f], K=256
__device__ float4 g_Wt1h[32 * G1DIM];         // Whh1^T  [k4][f], K=128 -> smem
__device__ float4 g_Wt2i[32 * G2DIM];         // Wih2^T  [k4][f], K=128
__device__ float4 g_Wt2h[ 8 * G2DIM];         // Whh2^T  [k4][f], K=32
__device__ float  g_WtInit[LAT * INITD];
__device__ float  g_WtIh0[LAT * G0DIM];

// ------------------------- helpers ------------------------------------------
__device__ __forceinline__ void ffma2(ull &d, ull a, ull b) {
    asm("fma.rn.f32x2 %0, %1, %2, %0;" : "+l"(d) : "l"(a), "l"(b));
}
__device__ __forceinline__ float hred(ull v) {
    float lo, hi;
    asm("mov.b64 {%0,%1}, %2;" : "=f"(lo), "=f"(hi) : "l"(v));
    return lo + hi;
}
__device__ __forceinline__ float sigf(float x) { return 1.0f / (1.0f + __expf(-x)); }
__device__ __forceinline__ float tanhfast(float x) {
    x = fmaxf(fminf(x, 40.0f), -40.0f);
    float e = __expf(-2.0f * x);
    return (1.0f - e) / (1.0f + e);
}

// ------------------------- prep kernels -------------------------------------
__global__ void k_prep_wt0(const float* __restrict__ Whh0) {
    int idx = blockIdx.x * blockDim.x + threadIdx.x;
    if (idx < G0DIM * 64) {
        int j = idx >> 6, k4 = idx & 63;
        const float* s = Whh0 + j * H1 + k4 * 4;
        g_Wt0[k4 * G0DIM + j] = make_float4(s[0], s[1], s[2], s[3]);
    }
}
__global__ void k_prep_wt1(const float* __restrict__ Wih1) {
    int idx = blockIdx.x * blockDim.x + threadIdx.x;
    if (idx < G1DIM * 64) {
        int j = idx >> 6, k4 = idx & 63;
        const float* s = Wih1 + j * H1 + k4 * 4;
        g_Wt1[k4 * G1DIM + j] = make_float4(s[0], s[1], s[2], s[3]);
    }
}
__global__ void k_prep_wt1h(const float* __restrict__ Whh1) {
    int idx = blockIdx.x * blockDim.x + threadIdx.x;
    if (idx < G1DIM * 32) {
        int j = idx >> 5, k4 = idx & 31;
        const float* s = Whh1 + j * H2 + k4 * 4;
        g_Wt1h[k4 * G1DIM + j] = make_float4(s[0], s[1], s[2], s[3]);
    }
}
__global__ void k_prep_wt2(const float* __restrict__ Wih2, const float* __restrict__ Whh2) {
    int idx = blockIdx.x * blockDim.x + threadIdx.x;
    if (idx < G2DIM * 32) {                 // Wih2: 96 x 128
        int f = idx >> 5, k4 = idx & 31;
        const float* s = Wih2 + f * H2 + k4 * 4;
        g_Wt2i[k4 * G2DIM + f] = make_float4(s[0], s[1], s[2], s[3]);
    }
    if (idx < G2DIM * 8) {                  // Whh2: 96 x 32
        int f = idx >> 3, k4 = idx & 7;
        const float* s = Whh2 + f * H3 + k4 * 4;
        g_Wt2h[k4 * G2DIM + f] = make_float4(s[0], s[1], s[2], s[3]);
    }
}
__global__ void k_prep_wtinit(const float* __restrict__ W_init) {
    int idx = blockIdx.x * blockDim.x + threadIdx.x;
    if (idx < INITD * LAT) {
        int o = idx / LAT, k = idx % LAT;
        g_WtInit[k * INITD + o] = W_init[idx];
    }
}
__global__ void k_prep_wtih0(const float* __restrict__ Wih0) {
    int idx = blockIdx.x * blockDim.x + threadIdx.x;
    if (idx < G0DIM * LAT) {
        int j = idx / LAT, k = idx % LAT;
        g_WtIh0[k * G0DIM + j] = Wih0[idx];
    }
}
__global__ void k_g0(const float* __restrict__ W_emb, const float* __restrict__ b_emb,
                     const float* __restrict__ bih0) {
    __shared__ float emb[LAT];
    int v = blockIdx.x;
    for (int k = threadIdx.x; k < LAT; k += blockDim.x)
        emb[k] = W_emb[k * VOCAB + v] + b_emb[k];
    __syncthreads();
    for (int j = threadIdx.x; j < G0DIM; j += blockDim.x) {
        float acc = bih0[j];
        for (int k = 0; k < LAT; k++)
            acc += emb[k] * g_WtIh0[k * G0DIM + j];
        g_G0[v * G0DIM + j] = acc;
    }
}
__global__ void k_init(const float* __restrict__ latent, const float* __restrict__ b_init) {
    __shared__ float lat[8 * LAT];
    int b0 = blockIdx.x * 8;
    for (int i = threadIdx.x; i < 8 * LAT; i += 256) {
        int r = i >> 9, k = i & 511;
        lat[i] = latent[(b0 + r) * LAT + k];
    }
    __syncthreads();
    for (int o = threadIdx.x; o < INITD; o += 256) {
        float bi = b_init[o];
        float acc[8];
#pragma unroll
        for (int r = 0; r < 8; r++) acc[r] = bi;
        for (int k = 0; k < LAT; k++) {
            float w = g_WtInit[k * INITD + o];
#pragma unroll
            for (int r = 0; r < 8; r++) acc[r] += w * lat[(r << 9) + k];
        }
#pragma unroll
        for (int r = 0; r < 8; r++) g_init[(b0 + r) * INITD + o] = acc[r];
    }
}

// ------------------------- main persistent GRU kernel -----------------------
// smem layout (floats)
#define O_WHH1 0                       // 384*32 float4 = 49152 floats
#define O_GATE 49152                   // 768*7 = 5376 floats (reused per layer)
#define O_H0   (O_GATE + 5376)        // 54528
#define O_H1   (O_H0 + BROWS * H1)    // 56320
#define O_H2   (O_H1 + BROWS * H2)    // 57216
#define O_LOG  (O_H2 + BROWS * H3)    // 57440
#define O_TOK  (O_LOG + 288)          // 57728
#define SMEM_FLOATS (O_TOK + 8)
#define SMEM_BYTES  (SMEM_FLOATS * 4)  // 230,944 bytes

__global__ void __launch_bounds__(NT, 1)
k_gru(const int* __restrict__ toks,
      const float* __restrict__ bhh0,
      const float* __restrict__ bih1, const float* __restrict__ bhh1,
      const float* __restrict__ bih2, const float* __restrict__ bhh2,
      const float* __restrict__ W_proj, const float* __restrict__ b_proj,
      float* __restrict__ out)
{
    extern __shared__ float sm[];
    float* sWhh1 = sm + O_WHH1;
    float* sGate = sm + O_GATE;
    float* h0    = sm + O_H0;
    float* h1    = sm + O_H1;
    float* h2    = sm + O_H2;
    float* slog  = sm + O_LOG;
    int*   stok  = (int*)(sm + O_TOK);

    const int tid  = threadIdx.x;
    const int base = blockIdx.x * BROWS;

    // --- load Whh1^T into smem ---
    {
        float4* d = (float4*)sWhh1;
        const float4* s = g_Wt1h;
        for (int i = tid; i < 32 * G1DIM; i += NT) d[i] = s[i];
    }
    // --- initial hidden states ---
    for (int i = tid; i < BROWS * H1; i += NT) {
        int r = i >> 8, k = i & 255;
        int b = base + r; if (b >= BB) b = BB - 1;
        h0[i] = g_init[b * INITD + k];
    }
    for (int i = tid; i < BROWS * H2; i += NT) {
        int r = i >> 7, k = i & 127;
        int b = base + r; if (b >= BB) b = BB - 1;
        h1[i] = g_init[b * INITD + H1 + k];
    }
    for (int i = tid; i < BROWS * H3; i += NT) {
        int r = i >> 5, k = i & 31;
        int b = base + r; if (b >= BB) b = BB - 1;
        h2[i] = g_init[b * INITD + H1 + H2 + k];
    }
    __syncthreads();

    for (int t = 0; t < SS; t++) {
        // tokens
        if (tid < BROWS) {
            int b = base + tid; if (b >= BB) b = BB - 1;
            stok[tid] = (t == 0) ? 1 : toks[b * SS + t];
        }
        __syncthreads();

        // ========== Layer 0 gh GEMM: h0 @ Whh0^T (768 feats, K=256) ========
        {
            const int f0 = tid * 2;
            ull a0[BROWS], a1[BROWS];
#pragma unroll
            for (int r = 0; r < BROWS; r++) { a0[r] = 0ull; a1[r] = 0ull; }
            const ulonglong2* Wp = (const ulonglong2*)g_Wt0 + f0;
            const ulonglong2* hb = (const ulonglong2*)h0;
            for (int k4 = 0; k4 < 64; k4++) {
                ulonglong2 w0 = Wp[0];
                ulonglong2 w1 = Wp[1];
#pragma unroll
                for (int r = 0; r < BROWS; r++) {
                    ulonglong2 hv = hb[r * 64 + k4];
                    ffma2(a0[r], w0.x, hv.x); ffma2(a0[r], w0.y, hv.y);
                    ffma2(a1[r], w1.x, hv.x); ffma2(a1[r], w1.y, hv.y);
                }
                Wp += G0DIM;
            }
#pragma unroll
            for (int r = 0; r < BROWS; r++) {
                sGate[f0 * 7 + r]       = hred(a0[r]);
                sGate[(f0 + 1) * 7 + r] = hred(a1[r]);
            }
        }
        __syncthreads();
        // ---- Layer 0 combine: 256 units x 7 rows ----
        for (int tau = tid; tau < H1 * BROWS; tau += NT) {
            int r = tau >> 8, i0 = tau & 255;
            const float* g = g_G0 + stok[r] * G0DIM;
            float hr = sGate[i0 * 7 + r]           + bhh0[i0];
            float hz = sGate[(i0 + H1) * 7 + r]    + bhh0[H1 + i0];
            float hn = sGate[(i0 + 2*H1) * 7 + r]  + bhh0[2*H1 + i0];
            float rg = sigf(g[i0] + hr);
            float zg = sigf(g[H1 + i0] + hz);
            float ng = tanhfast(g[2*H1 + i0] + rg * hn);
            float hp = h0[r * H1 + i0];
            h0[r * H1 + i0] = (1.0f - zg) * ng + zg * hp;
        }
        __syncthreads();

        // ========== Layer 1 GEMM: gi (K=256) + gh (K=128), 384 feats =======
        {
            const int f = tid;
            ull ai[BROWS], ah[BROWS];
#pragma unroll
            for (int r = 0; r < BROWS; r++) { ai[r] = 0ull; ah[r] = 0ull; }
            const ulonglong2* Wp = (const ulonglong2*)g_Wt1 + f;
            const ulonglong2* hb = (const ulonglong2*)h0;
            for (int k4 = 0; k4 < 64; k4++) {
                ulonglong2 w = Wp[0];
#pragma unroll
                for (int r = 0; r < BROWS; r++) {
                    ulonglong2 hv = hb[r * 64 + k4];
                    ffma2(ai[r], w.x, hv.x); ffma2(ai[r], w.y, hv.y);
                }
                Wp += G1DIM;
            }
            const ulonglong2* Wh = (const ulonglong2*)sWhh1 + f;
            const ulonglong2* h1b = (const ulonglong2*)h1;
            for (int k4 = 0; k4 < 32; k4++) {
                ulonglong2 w = Wh[0];
#pragma unroll
                for (int r = 0; r < BROWS; r++) {
                    ulonglong2 hv = h1b[r * 32 + k4];
                    ffma2(ah[r], w.x, hv.x); ffma2(ah[r], w.y, hv.y);
                }
                Wh += G1DIM;
            }
#pragma unroll
            for (int r = 0; r < BROWS; r++) {
                sGate[f * 7 + r]             = hred(ai[r]);
                sGate[G1DIM * 7 + f * 7 + r] = hred(ah[r]);
            }
        }
        __syncthreads();
        // ---- Layer 1 combine: 128 units x 7 rows ----
        for (int tau = tid; tau < H2 * BROWS; tau += NT) {
            int r = tau >> 7, j = tau & 127;
            float gir = sGate[j * 7 + r]            + bih1[j];
            float giz = sGate[(j + H2) * 7 + r]     + bih1[H2 + j];
            float gin = sGate[(j + 2*H2) * 7 + r]   + bih1[2*H2 + j];
            float ghr = sGate[G1DIM*7 + j * 7 + r]          + bhh1[j];
            float ghz = sGate[G1DIM*7 + (j + H2) * 7 + r]   + bhh1[H2 + j];
            float ghn = sGate[G1DIM*7 + (j + 2*H2) * 7 + r] + bhh1[2*H2 + j];
            float rg = sigf(gir + ghr);
            float zg = sigf(giz + ghz);
            float ng = tanhfast(gin + rg * ghn);
            float hp = h1[r * H2 + j];
            h1[r * H2 + j] = (1.0f - zg) * ng + zg * hp;
        }
        __syncthreads();

        // ========== Layer 2 GEMM: gi (96 feats K=128) + gh (96 feats K=32) =
        {
            if (tid < G2DIM) {
                const int f = tid;
                ull a[BROWS];
#pragma unroll
                for (int r = 0; r < BROWS; r++) a[r] = 0ull;
                const ulonglong2* Wp = (const ulonglong2*)g_Wt2i + f;
                const ulonglong2* hb = (const ulonglong2*)h1;
                for (int k4 = 0; k4 < 32; k4++) {
                    ulonglong2 w = Wp[0];
#pragma unroll
                    for (int r = 0; r < BROWS; r++) {
                        ulonglong2 hv = hb[r * 32 + k4];
                        ffma2(a[r], w.x, hv.x); ffma2(a[r], w.y, hv.y);
                    }
                    Wp += G2DIM;
                }
#pragma unroll
                for (int r = 0; r < BROWS; r++) sGate[f * 7 + r] = hred(a[r]);
            } else if (tid < 2 * G2DIM) {
                const int f = tid - G2DIM;
                ull a[BROWS];
#pragma unroll
                for (int r = 0; r < BROWS; r++) a[r] = 0ull;
                const ulonglong2* Wp = (const ulonglong2*)g_Wt2h + f;
                const ulonglong2* hb = (const ulonglong2*)h2;
                for (int k4 = 0; k4 < 8; k4++) {
                    ulonglong2 w = Wp[0];
#pragma unroll
                    for (int r = 0; r < BROWS; r++) {
                        ulonglong2 hv = hb[r * 8 + k4];
                        ffma2(a[r], w.x, hv.x); ffma2(a[r], w.y, hv.y);
                    }
                    Wp += G2DIM;
                }
#pragma unroll
                for (int r = 0; r < BROWS; r++)
                    sGate[G2DIM * 7 + f * 7 + r] = hred(a[r]);
            }
        }
        __syncthreads();
        // ---- Layer 2 combine: 32 units x 7 rows (224 tasks) ----
        if (tid < H3 * BROWS) {
            int r = tid >> 5, i2 = tid & 31;
            float gir = sGate[i2 * 7 + r]          + bih2[i2];
            float giz = sGate[(i2 + H3) * 7 + r]   + bih2[H3 + i2];
            float gin = sGate[(i2 + 2*H3) * 7 + r] + bih2[2*H3 + i2];
            float ghr = sGate[G2DIM*7 + i2 * 7 + r]          + bhh2[i2];
            float ghz = sGate[G2DIM*7 + (i2 + H3) * 7 + r]   + bhh2[H3 + i2];
            float ghn = sGate[G2DIM*7 + (i2 + 2*H3) * 7 + r] + bhh2[2*H3 + i2];
            float rg = sigf(gir + ghr);
            float zg = sigf(giz + ghz);
            float ng = tanhfast(gin + rg * ghn);
            float hp = h2[r * H3 + i2];
            h2[r * H3 + i2] = (1.0f - zg) * ng + zg * hp;
        }
        __syncthreads();

        // ========== logits + store =========================================
        if (tid < BROWS * VOCAB) {
            int r = tid / VOCAB, o = tid % VOCAB;
            const float4* wp = (const float4*)(W_proj + o * H3);
            const float4* hp = (const float4*)(h2 + r * H3);
            float acc = b_proj[o];
#pragma unroll
            for (int q = 0; q < 8; q++) {
                float4 w = wp[q];
                float4 h = hp[q];
                acc += w.x * h.x + w.y * h.y + w.z * h.z + w.w * h.w;
            }
            slog[r * VOCAB + o] = acc;
            int b = base + r;
            if (b < BB) out[(b * SS + t) * VOCAB + o] = acc;
        }
        __syncthreads();
        // argmax (first max index)
        if (tid < BROWS) {
            float best = slog[tid * VOCAB];
            int   bi   = 0;
            for (int o = 1; o < VOCAB; o++) {
                float v = slog[tid * VOCAB + o];
                if (v > best) { best = v; bi = o; }
            }
            int b = base + tid;
            if (b < BB) out[PRED_OFF + b * SS + t] = (float)bi;
        }
        __syncthreads();
    }
}

// ------------------------- launch -------------------------------------------
extern "C" void kernel_launch(void* const* d_in, const int* in_sizes, int n_in,
                              void* d_out, int out_size) {
    const float* latent  = (const float*)d_in[0];
    const int*   ttok    = (const int*)  d_in[1];
    const float* W_emb   = (const float*)d_in[2];
    const float* b_emb   = (const float*)d_in[3];
    const float* W_init  = (const float*)d_in[4];
    const float* b_init  = (const float*)d_in[5];
    const float* Wih0    = (const float*)d_in[6];
    const float* Whh0    = (const float*)d_in[7];
    const float* bih0    = (const float*)d_in[8];
    const float* bhh0    = (const float*)d_in[9];
    const float* Wih1    = (const float*)d_in[10];
    const float* Whh1    = (const float*)d_in[11];
    const float* bih1    = (const float*)d_in[12];
    const float* bhh1    = (const float*)d_in[13];
    const float* Wih2    = (const float*)d_in[14];
    const float* Whh2    = (const float*)d_in[15];
    const float* bih2    = (const float*)d_in[16];
    const float* bhh2    = (const float*)d_in[17];
    const float* W_proj  = (const float*)d_in[18];
    const float* b_proj  = (const float*)d_in[19];
    float* out = (float*)d_out;

    k_prep_wt0  <<<(G0DIM * 64 + 255) / 256, 256>>>(Whh0);
    k_prep_wt1  <<<(G1DIM * 64 + 255) / 256, 256>>>(Wih1);
    k_prep_wt1h <<<(G1DIM * 32 + 255) / 256, 256>>>(Whh1);
    k_prep_wt2  <<<(G2DIM * 32 + 255) / 256, 256>>>(Wih2, Whh2);
    k_prep_wtinit<<<(INITD * LAT + 255) / 256, 256>>>(W_init);
    k_prep_wtih0<<<(G0DIM * LAT + 255) / 256, 256>>>(Wih0);
    k_g0  <<<VOCAB, 256>>>(W_emb, b_emb, bih0);
    k_init<<<BB / 8, 256>>>(latent, b_init);

    cudaFuncSetAttribute(k_gru, cudaFuncAttributeMaxDynamicSharedMemorySize, SMEM_BYTES);
    k_gru<<<NCTA, NT, SMEM_BYTES>>>(ttok, bhh0, bih1, bhh1, bih2, bhh2,
                                    W_proj, b_proj, out);
}

// round 4
// speedup vs baseline: 1.4854x; 1.0122x over previous
#include <cuda_runtime.h>
#include <cuda_bf16.h>

// Problem constants
#define BB     1024
#define SS     350
#define VOCAB  41
#define LAT    512
#define H1     256
#define H2     128
#define H3     32
#define G0DIM  768
#define G1DIM  384
#define G2DIM  96
#define INITD  416
#define BROWS  8
#define NCTA   128   // 128*8 = 1024 exactly
#define NT     384
#define PRED_OFF (BB*SS*VOCAB)
#define WHH1_SM_SLICES 28     // k4 slices of Whh1 kept in smem (of 32)

typedef unsigned long long ull;

// ------------------------- device scratch -----------------------------------
__device__ float  g_G0[VOCAB * G0DIM];        // gi0 table (includes bih0)
__device__ float  g_init[BB * INITD];
__device__ float4 g_Wt0 [64 * G0DIM];         // Whh0^T  [k4][f], K=256
__device__ float4 g_Wt1 [64 * G1DIM];         // Wih1^T  [k4][f], K=256
__device__ float4 g_Wt1h[32 * G1DIM];         // Whh1^T  [k4][f], K=128
__device__ float4 g_Wt2i[32 * G2DIM];         // Wih2^T  [k4][f], K=128
__device__ float4 g_Wt2h[ 8 * G2DIM];         // Whh2^T  [k4][f], K=32
__device__ float  g_WtInit[LAT * INITD];
__device__ float  g_WtIh0[LAT * G0DIM];

// ------------------------- helpers ------------------------------------------
__device__ __forceinline__ void ffma2(ull &d, ull a, ull b) {
    asm("fma.rn.f32x2 %0, %1, %2, %0;" : "+l"(d) : "l"(a), "l"(b));
}
__device__ __forceinline__ ull packf2(float lo, float hi) {
    ull v; asm("mov.b64 %0, {%1,%2};" : "=l"(v) : "f"(lo), "f"(hi)); return v;
}
__device__ __forceinline__ float hred(ull v) {
    float lo, hi;
    asm("mov.b64 {%0,%1}, %2;" : "=f"(lo), "=f"(hi) : "l"(v));
    return lo + hi;
}
__device__ __forceinline__ float sigf(float x) { return 1.0f / (1.0f + __expf(-x)); }

// ------------------------- prep kernels -------------------------------------
__global__ void k_prep_wt0(const float* __restrict__ Whh0) {
    int idx = blockIdx.x * blockDim.x + threadIdx.x;
    if (idx < G0DIM * 64) {
        int j = idx >> 6, k4 = idx & 63;
        const float* s = Whh0 + j * H1 + k4 * 4;
        g_Wt0[k4 * G0DIM + j] = make_float4(s[0], s[1], s[2], s[3]);
    }
}
__global__ void k_prep_wt1(const float* __restrict__ Wih1) {
    int idx = blockIdx.x * blockDim.x + threadIdx.x;
    if (idx < G1DIM * 64) {
        int j = idx >> 6, k4 = idx & 63;
        const float* s = Wih1 + j * H1 + k4 * 4;
        g_Wt1[k4 * G1DIM + j] = make_float4(s[0], s[1], s[2], s[3]);
    }
}
__global__ void k_prep_wt1h(const float* __restrict__ Whh1) {
    int idx = blockIdx.x * blockDim.x + threadIdx.x;
    if (idx < G1DIM * 32) {
        int j = idx >> 5, k4 = idx & 31;
        const float* s = Whh1 + j * H2 + k4 * 4;
        g_Wt1h[k4 * G1DIM + j] = make_float4(s[0], s[1], s[2], s[3]);
    }
}
__global__ void k_prep_wt2(const float* __restrict__ Wih2, const float* __restrict__ Whh2) {
    int idx = blockIdx.x * blockDim.x + threadIdx.x;
    if (idx < G2DIM * 32) {
        int f = idx >> 5, k4 = idx & 31;
        const float* s = Wih2 + f * H2 + k4 * 4;
        g_Wt2i[k4 * G2DIM + f] = make_float4(s[0], s[1], s[2], s[3]);
    }
    if (idx < G2DIM * 8) {
        int f = idx >> 3, k4 = idx & 7;
        const float* s = Whh2 + f * H3 + k4 * 4;
        g_Wt2h[k4 * G2DIM + f] = make_float4(s[0], s[1], s[2], s[3]);
    }
}
__global__ void k_prep_wtinit(const float* __restrict__ W_init) {
    int idx = blockIdx.x * blockDim.x + threadIdx.x;
    if (idx < INITD * LAT) {
        int o = idx / LAT, k = idx % LAT;
        g_WtInit[k * INITD + o] = W_init[idx];
    }
}
__global__ void k_prep_wtih0(const float* __restrict__ Wih0) {
    int idx = blockIdx.x * blockDim.x + threadIdx.x;
    if (idx < G0DIM * LAT) {
        int j = idx / LAT, k = idx % LAT;
        g_WtIh0[k * G0DIM + j] = Wih0[idx];
    }
}
__global__ void k_g0(const float* __restrict__ W_emb, const float* __restrict__ b_emb,
                     const float* __restrict__ bih0) {
    __shared__ float emb[LAT];
    int v = blockIdx.x;
    for (int k = threadIdx.x; k < LAT; k += blockDim.x)
        emb[k] = W_emb[k * VOCAB + v] + b_emb[k];
    __syncthreads();
    for (int j = threadIdx.x; j < G0DIM; j += blockDim.x) {
        float acc = bih0[j];
        for (int k = 0; k < LAT; k++)
            acc += emb[k] * g_WtIh0[k * G0DIM + j];
        g_G0[v * G0DIM + j] = acc;
    }
}
__global__ void k_init(const float* __restrict__ latent, const float* __restrict__ b_init) {
    __shared__ float lat[8 * LAT];
    int b0 = blockIdx.x * 8;
    for (int i = threadIdx.x; i < 8 * LAT; i += 256) {
        int r = i >> 9, k = i & 511;
        lat[i] = latent[(b0 + r) * LAT + k];
    }
    __syncthreads();
    for (int o = threadIdx.x; o < INITD; o += 256) {
        float bi = b_init[o];
        float acc[8];
#pragma unroll
        for (int r = 0; r < 8; r++) acc[r] = bi;
        for (int k = 0; k < LAT; k++) {
            float w = g_WtInit[k * INITD + o];
#pragma unroll
            for (int r = 0; r < 8; r++) acc[r] += w * lat[(r << 9) + k];
        }
#pragma unroll
        for (int r = 0; r < 8; r++) g_init[(b0 + r) * INITD + o] = acc[r];
    }
}

// ------------------------- main persistent GRU kernel -----------------------
// smem layout (floats)
#define O_WHH1 0                                      // 28*384 float4 = 43008 floats
#define O_GA   (WHH1_SM_SLICES * G1DIM * 4)           // 43008; size 6144
#define O_GB   (O_GA + 6144)                          // 49152; size 3072
#define O_GC   (O_GB + 3072)                          // 52224; size 768
#define O_H0   (O_GC + 768)                           // 52992; 2048
#define O_H1   (O_H0 + BROWS * H1)                    // 55040; 1024
#define O_H2   (O_H1 + BROWS * H2)                    // 56064; 256
#define O_TOK  (O_H2 + BROWS * H3)                    // 56320
#define SMEM_FLOATS (O_TOK + 8)
#define SMEM_BYTES  (SMEM_FLOATS * 4)                 // 225,312 bytes

__global__ void __launch_bounds__(NT, 1)
k_gru(const int* __restrict__ toks,
      const float* __restrict__ bhh0,
      const float* __restrict__ bih1, const float* __restrict__ bhh1,
      const float* __restrict__ bih2, const float* __restrict__ bhh2,
      const float* __restrict__ W_proj, const float* __restrict__ b_proj,
      float* __restrict__ out)
{
    extern __shared__ float sm[];
    float* sGA  = sm + O_GA;      // region A (stride 768 / 384 / 96 reuse)
    float* sGB  = sm + O_GB;      // gh1 region (stride 384)
    float* sGC  = sm + O_GC;      // gh2 region (stride 96)
    float* h0   = sm + O_H0;
    float* h1   = sm + O_H1;
    float* h2   = sm + O_H2;
    int*   stok = (int*)(sm + O_TOK);

    const int tid  = threadIdx.x;
    const int lane = tid & 31;
    const int wrp  = tid >> 5;
    const int base = blockIdx.x * BROWS;
    const int rot  = (blockIdx.x * 37) & 63;

    // --- load Whh1^T slices 0..27 into smem ---
    {
        float4* d = (float4*)(sm + O_WHH1);
        const float4* s = g_Wt1h;
        for (int i = tid; i < WHH1_SM_SLICES * G1DIM; i += NT) d[i] = s[i];
    }
    // --- initial hidden states ---
    for (int i = tid; i < BROWS * H1; i += NT) {
        int r = i >> 8, k = i & 255;
        h0[i] = g_init[(base + r) * INITD + k];
    }
    for (int i = tid; i < BROWS * H2; i += NT) {
        int r = i >> 7, k = i & 127;
        h1[i] = g_init[(base + r) * INITD + H1 + k];
    }
    for (int i = tid; i < BROWS * H3; i += NT) {
        int r = i >> 5, k = i & 31;
        h2[i] = g_init[(base + r) * INITD + H1 + H2 + k];
    }
    if (tid < BROWS) stok[tid] = 1;   // SOS for t=0

    // --- per-thread preloads (fixed assignments) ---
    const int f0 = tid * 2;
    const float b0a = bhh0[f0], b0b = bhh0[f0 + 1];
    const float b1i = bih1[tid], b1h = bhh1[tid];
    float b2i = 0.0f, b2h = 0.0f;
    if (tid < G2DIM) { b2i = bih2[tid]; b2h = bhh2[tid]; }
    float bp0 = 0.0f, bp1 = 0.0f;
    if (wrp < BROWS) { bp0 = b_proj[lane]; if (lane < 9) bp1 = b_proj[32 + lane]; }
    __syncthreads();

    for (int t = 0; t <= SS; t++) {
        // ===== fused: logits+argmax of step t-1 (warps 0..7) + phase A ======
        if (t > 0 && wrp < BROWS) {
            const int r = wrp, b = base + r, tprev = t - 1;
            const float4* hp = (const float4*)(h2 + r * H3);
            float4 hv[8];
#pragma unroll
            for (int q = 0; q < 8; q++) hv[q] = hp[q];
            float acc0 = bp0, acc1 = bp1;
            {
                const float4* wp = (const float4*)(W_proj + lane * H3);
#pragma unroll
                for (int q = 0; q < 8; q++) {
                    float4 w = wp[q];
                    acc0 += w.x * hv[q].x + w.y * hv[q].y + w.z * hv[q].z + w.w * hv[q].w;
                }
            }
            if (lane < 9) {
                const float4* wp = (const float4*)(W_proj + (32 + lane) * H3);
#pragma unroll
                for (int q = 0; q < 8; q++) {
                    float4 w = wp[q];
                    acc1 += w.x * hv[q].x + w.y * hv[q].y + w.z * hv[q].z + w.w * hv[q].w;
                }
            }
            float* orow = out + (size_t)(b * SS + tprev) * VOCAB;
            orow[lane] = acc0;
            if (lane < 9) orow[32 + lane] = acc1;
            // warp argmax, first-max-index semantics
            float bv = acc0; int bo = lane;
            if (lane < 9 && acc1 > bv) { bv = acc1; bo = 32 + lane; }
#pragma unroll
            for (int off = 16; off; off >>= 1) {
                float ov = __shfl_xor_sync(0xffffffffu, bv, off);
                int   oo = __shfl_xor_sync(0xffffffffu, bo, off);
                if (ov > bv || (ov == bv && oo < bo)) { bv = ov; bo = oo; }
            }
            if (lane == 0) out[PRED_OFF + b * SS + tprev] = (float)bo;
        }
        if (t < SS) {
            // ---- gh0 GEMM: feats f0, f0+1, K=256 over h0 ----
            {
                ull a0[BROWS], a1[BROWS];
                if (f0 < 512) {
#pragma unroll
                    for (int r = 0; r < BROWS; r++) {
                        float2 g = *(const float2*)&g_G0[stok[r] * G0DIM + f0];
                        a0[r] = packf2(g.x + b0a, 0.0f);
                        a1[r] = packf2(g.y + b0b, 0.0f);
                    }
                } else {
#pragma unroll
                    for (int r = 0; r < BROWS; r++) {
                        a0[r] = packf2(b0a, 0.0f);
                        a1[r] = packf2(b0b, 0.0f);
                    }
                }
                const ulonglong2* W  = (const ulonglong2*)g_Wt0;
                const ulonglong2* hb = (const ulonglong2*)h0;
                int k4 = rot;
#pragma unroll 2
                for (int kk = 0; kk < 64; kk++) {
                    ulonglong2 w0 = W[k4 * G0DIM + f0];
                    ulonglong2 w1 = W[k4 * G0DIM + f0 + 1];
#pragma unroll
                    for (int r = 0; r < BROWS; r++) {
                        ulonglong2 hv = hb[r * 64 + k4];
                        ffma2(a0[r], w0.x, hv.x); ffma2(a0[r], w0.y, hv.y);
                        ffma2(a1[r], w1.x, hv.x); ffma2(a1[r], w1.y, hv.y);
                    }
                    k4 = (k4 + 1) & 63;
                }
#pragma unroll
                for (int r = 0; r < BROWS; r++) {
                    sGA[r * G0DIM + f0]     = hred(a0[r]);
                    sGA[r * G0DIM + f0 + 1] = hred(a1[r]);
                }
            }
            // ---- gh1 GEMM: feat tid, K=128 over h1 ----
            {
                ull a[BROWS];
#pragma unroll
                for (int r = 0; r < BROWS; r++) a[r] = packf2(b1h, 0.0f);
                const ulonglong2* Ws = (const ulonglong2*)(sm + O_WHH1);
                const ulonglong2* Wg = (const ulonglong2*)g_Wt1h;
                const ulonglong2* hb = (const ulonglong2*)h1;
                for (int k4 = 0; k4 < 32; k4++) {
                    ulonglong2 w = (k4 < WHH1_SM_SLICES) ? Ws[k4 * G1DIM + tid]
                                                         : Wg[k4 * G1DIM + tid];
#pragma unroll
                    for (int r = 0; r < BROWS; r++) {
                        ulonglong2 hv = hb[r * 32 + k4];
                        ffma2(a[r], w.x, hv.x); ffma2(a[r], w.y, hv.y);
                    }
                }
#pragma unroll
                for (int r = 0; r < BROWS; r++) sGB[r * G1DIM + tid] = hred(a[r]);
            }
            // ---- gh2 GEMM: feats 0..95 (tid<96), K=32 over h2 ----
            if (tid < G2DIM) {
                ull a[BROWS];
#pragma unroll
                for (int r = 0; r < BROWS; r++) a[r] = packf2(b2h, 0.0f);
                const ulonglong2* W  = (const ulonglong2*)g_Wt2h;
                const ulonglong2* hb = (const ulonglong2*)h2;
#pragma unroll
                for (int k4 = 0; k4 < 8; k4++) {
                    ulonglong2 w = W[k4 * G2DIM + tid];
#pragma unroll
                    for (int r = 0; r < BROWS; r++) {
                        ulonglong2 hv = hb[r * 8 + k4];
                        ffma2(a[r], w.x, hv.x); ffma2(a[r], w.y, hv.y);
                    }
                }
#pragma unroll
                for (int r = 0; r < BROWS; r++) sGC[r * G2DIM + tid] = hred(a[r]);
            }
        }
        __syncthreads();   // S1

        // ===== combine0: new h0 =====
        if (t < SS) {
            for (int tau = tid; tau < BROWS * H1; tau += NT) {
                int r = tau >> 8, i = tau & 255;
                float pr  = sGA[r * G0DIM + i];
                float pz  = sGA[r * G0DIM + H1 + i];
                float ghn = sGA[r * G0DIM + 2 * H1 + i];
                float gin = g_G0[stok[r] * G0DIM + 2 * H1 + i];
                float rg = sigf(pr), zg = sigf(pz);
                float ng = tanhf(fmaf(rg, ghn, gin));
                float hp = h0[r * H1 + i];
                h0[r * H1 + i] = fmaf(zg, hp - ng, ng);
            }
        }
        __syncthreads();   // S2

        // ===== gi1 GEMM: feat tid, K=256 over new h0 =====
        if (t < SS) {
            ull a[BROWS];
#pragma unroll
            for (int r = 0; r < BROWS; r++) a[r] = packf2(b1i, 0.0f);
            const ulonglong2* W  = (const ulonglong2*)g_Wt1;
            const ulonglong2* hb = (const ulonglong2*)h0;
            int k4 = rot;
#pragma unroll 2
            for (int kk = 0; kk < 64; kk++) {
                ulonglong2 w = W[k4 * G1DIM + tid];
#pragma unroll
                for (int r = 0; r < BROWS; r++) {
                    ulonglong2 hv = hb[r * 64 + k4];
                    ffma2(a[r], w.x, hv.x); ffma2(a[r], w.y, hv.y);
                }
                k4 = (k4 + 1) & 63;
            }
#pragma unroll
            for (int r = 0; r < BROWS; r++) sGA[r * G1DIM + tid] = hred(a[r]);
        }
        __syncthreads();   // S3

        // ===== combine1: new h1 =====
        if (t < SS) {
            for (int tau = tid; tau < BROWS * H2; tau += NT) {
                int r = tau >> 7, j = tau & 127;
                float pr  = sGA[r * G1DIM + j]          + sGB[r * G1DIM + j];
                float pz  = sGA[r * G1DIM + H2 + j]     + sGB[r * G1DIM + H2 + j];
                float gin = sGA[r * G1DIM + 2 * H2 + j];
                float ghn = sGB[r * G1DIM + 2 * H2 + j];
                float rg = sigf(pr), zg = sigf(pz);
                float ng = tanhf(fmaf(rg, ghn, gin));
                float hp = h1[r * H2 + j];
                h1[r * H2 + j] = fmaf(zg, hp - ng, ng);
            }
        }
        __syncthreads();   // S4

        // ===== gi2 GEMM: 96 feats, K=128 over new h1, split-K in 2 =====
        if (t < SS && tid < 2 * G2DIM) {
            const int f  = (tid < G2DIM) ? tid : tid - G2DIM;
            const int k0 = (tid < G2DIM) ? 0 : 16;
            ull a[BROWS];
            ull ini = (tid < G2DIM) ? packf2(b2i, 0.0f) : 0ull;
#pragma unroll
            for (int r = 0; r < BROWS; r++) a[r] = ini;
            const ulonglong2* W  = (const ulonglong2*)g_Wt2i;
            const ulonglong2* hb = (const ulonglong2*)h1;
#pragma unroll
            for (int kk = 0; kk < 16; kk++) {
                int k4 = k0 + kk;
                ulonglong2 w = W[k4 * G2DIM + f];
#pragma unroll
                for (int r = 0; r < BROWS; r++) {
                    ulonglong2 hv = hb[r * 32 + k4];
                    ffma2(a[r], w.x, hv.x); ffma2(a[r], w.y, hv.y);
                }
            }
            float* dst = sGA + ((tid < G2DIM) ? 0 : BROWS * G2DIM);
#pragma unroll
            for (int r = 0; r < BROWS; r++) dst[r * G2DIM + f] = hred(a[r]);
        }
        __syncthreads();   // S5

        // ===== combine2: new h2; prefetch next tokens =====
        if (t < SS) {
            if (tid < BROWS * H3) {
                int r = tid >> 5, i = tid & 31;
                float* A = sGA;
                float* Bp = sGA + BROWS * G2DIM;
                float pr  = A[r * G2DIM + i]          + Bp[r * G2DIM + i]          + sGC[r * G2DIM + i];
                float pz  = A[r * G2DIM + H3 + i]     + Bp[r * G2DIM + H3 + i]     + sGC[r * G2DIM + H3 + i];
                float gin = A[r * G2DIM + 2 * H3 + i] + Bp[r * G2DIM + 2 * H3 + i];
                float ghn = sGC[r * G2DIM + 2 * H3 + i];
                float rg = sigf(pr), zg = sigf(pz);
                float ng = tanhf(fmaf(rg, ghn, gin));
                float hp = h2[r * H3 + i];
                h2[r * H3 + i] = fmaf(zg, hp - ng, ng);
            }
            if (t + 1 < SS && tid < BROWS)
                stok[tid] = toks[(base + tid) * SS + (t + 1)];
        }
        __syncthreads();   // S6
    }
}

// ------------------------- launch -------------------------------------------
extern "C" void kernel_launch(void* const* d_in, const int* in_sizes, int n_in,
                              void* d_out, int out_size) {
    const float* latent  = (const float*)d_in[0];
    const int*   ttok    = (const int*)  d_in[1];
    const float* W_emb   = (const float*)d_in[2];
    const float* b_emb   = (const float*)d_in[3];
    const float* W_init  = (const float*)d_in[4];
    const float* b_init  = (const float*)d_in[5];
    const float* Wih0    = (const float*)d_in[6];
    const float* Whh0    = (const float*)d_in[7];
    const float* bih0    = (const float*)d_in[8];
    const float* bhh0    = (const float*)d_in[9];
    const float* Wih1    = (const float*)d_in[10];
    const float* Whh1    = (const float*)d_in[11];
    const float* bih1    = (const float*)d_in[12];
    const float* bhh1    = (const float*)d_in[13];
    const float* Wih2    = (const float*)d_in[14];
    const float* Whh2    = (const float*)d_in[15];
    const float* bih2    = (const float*)d_in[16];
    const float* bhh2    = (const float*)d_in[17];
    const float* W_proj  = (const float*)d_in[18];
    const float* b_proj  = (const float*)d_in[19];
    float* out = (float*)d_out;

    k_prep_wt0   <<<(G0DIM * 64 + 255) / 256, 256>>>(Whh0);
    k_prep_wt1   <<<(G1DIM * 64 + 255) / 256, 256>>>(Wih1);
    k_prep_wt1h  <<<(G1DIM * 32 + 255) / 256, 256>>>(Whh1);
    k_prep_wt2   <<<(G2DIM * 32 + 255) / 256, 256>>>(Wih2, Whh2);
    k_prep_wtinit<<<(INITD * LAT + 255) / 256, 256>>>(W_init);
    k_prep_wtih0 <<<(G0DIM * LAT + 255) / 256, 256>>>(Wih0);
    k_g0  <<<VOCAB, 256>>>(W_emb, b_emb, bih0);
    k_init<<<BB / 8, 256>>>(latent, b_init);

    cudaFuncSetAttribute(k_gru, cudaFuncAttributeMaxDynamicSharedMemorySize, SMEM_BYTES);
    k_gru<<<NCTA, NT, SMEM_BYTES>>>(ttok, bhh0, bih1, bhh1, bih2, bhh2,
                                    W_proj, b_proj, out);
}